// round 1
// baseline (speedup 1.0000x reference)
#include <cuda_runtime.h>
#include <math.h>

// Scalar accumulators in device globals (no allocation allowed).
// g_acc[0] = sum over rows of (C*lse - sumx)        -> loss * N
// g_acc[1] = sum over rows of (x[target] - lse)     -> -nll * N
// g_acc[2] = sum over first C rows of per_elem      -> correction * C
__device__ double g_acc[3];

__global__ void zero_acc_kernel() {
    if (threadIdx.x < 3) g_acc[threadIdx.x] = 0.0;
}

// One warp per row. C <= 1024 assumed (here C = 1000 -> 250 float4, <= 8 per lane).
__global__ void __launch_bounds__(256)
lsce_main_kernel(const float* __restrict__ out,
                 const long long* __restrict__ tgt,
                 int N, int C) {
    const int lane = threadIdx.x & 31;
    const int wib  = threadIdx.x >> 5;            // warp in block (0..7)
    const int row  = blockIdx.x * 8 + wib;        // one row per warp

    __shared__ double sh[8][3];

    double t0 = 0.0, t1 = 0.0, t2 = 0.0;

    if (row < N) {
        const float4* __restrict__ rp =
            reinterpret_cast<const float4*>(out + (size_t)row * (size_t)C);
        const int nv = C >> 2;                    // 250 float4 per row
        const int t  = (int)tgt[row];

        // Stage this lane's slice of the row in registers (<= 8 float4).
        float4 v[8];
        #pragma unroll
        for (int k = 0; k < 8; k++) {
            int j = lane + 32 * k;
            if (j < nv) v[k] = __ldg(&rp[j]);
        }

        // Sweep 1: local max/argmax (first occurrence), sum, picked.
        float m = -INFINITY;
        int   mi = C;
        float sumx = 0.f;
        float picked = 0.f;
        #pragma unroll
        for (int k = 0; k < 8; k++) {
            int j = lane + 32 * k;
            if (j < nv) {
                const float x0 = v[k].x, x1 = v[k].y, x2 = v[k].z, x3 = v[k].w;
                const int b = 4 * j;
                sumx += (x0 + x1) + (x2 + x3);
                if (x0 > m) { m = x0; mi = b;     }
                if (x1 > m) { m = x1; mi = b + 1; }
                if (x2 > m) { m = x2; mi = b + 2; }
                if (x3 > m) { m = x3; mi = b + 3; }
                if (t >= b && t < b + 4) {
                    picked = (t == b) ? x0 : (t == b + 1) ? x1 : (t == b + 2) ? x2 : x3;
                }
            }
        }

        // Warp reduce: (max, argmax first-occurrence), sumx, picked.
        #pragma unroll
        for (int off = 16; off; off >>= 1) {
            const float om = __shfl_xor_sync(0xffffffffu, m,  off);
            const int   oi = __shfl_xor_sync(0xffffffffu, mi, off);
            if (om > m || (om == m && oi < mi)) { m = om; mi = oi; }
            sumx   += __shfl_xor_sync(0xffffffffu, sumx,   off);
            picked += __shfl_xor_sync(0xffffffffu, picked, off);
        }

        // Sweep 2: sum of exp(x - rowmax).
        float s = 0.f;
        #pragma unroll
        for (int k = 0; k < 8; k++) {
            int j = lane + 32 * k;
            if (j < nv) {
                s += __expf(v[k].x - m) + __expf(v[k].y - m)
                   + __expf(v[k].z - m) + __expf(v[k].w - m);
            }
        }
        #pragma unroll
        for (int off = 16; off; off >>= 1)
            s += __shfl_xor_sync(0xffffffffu, s, off);

        if (lane == 0) {
            const float lse = m + __logf(s);
            t0 = (double)C * (double)lse - (double)sumx;   // C*lse - sum(x)
            t1 = (double)picked - (double)lse;             // log_pred at target
            if (row < C) {
                const long long hat = (long long)mi;
                const long long tt  = (long long)t;
                const long long lt  = hat + tt;
                const long long ad  = llabs(hat - tt);
                const double EPSd = 0.1;
                const double POSd = 1.0 / 0.32447699714575207;
                const double NEGd = 0.5945275813408382;
                t2 = (lt >= 2) ? (EPSd * POSd)
                   : ((lt == 1 && ad != 1) ? -(EPSd * NEGd) : 0.0);
            }
        }
    }

    if (lane == 0) { sh[wib][0] = t0; sh[wib][1] = t1; sh[wib][2] = t2; }
    __syncthreads();

    if (threadIdx.x == 0) {
        double a0 = 0.0, a1 = 0.0, a2 = 0.0;
        #pragma unroll
        for (int i = 0; i < 8; i++) { a0 += sh[i][0]; a1 += sh[i][1]; a2 += sh[i][2]; }
        atomicAdd(&g_acc[0], a0);
        atomicAdd(&g_acc[1], a1);
        atomicAdd(&g_acc[2], a2);
    }
}

__global__ void finalize_kernel(float* __restrict__ outp, int N, int C) {
    const double EPSd = 0.1;
    const double loss = g_acc[0] / (double)N;
    const double nll  = -(g_acc[1] / (double)N);
    const double corr = g_acc[2] / (double)C;
    outp[0] = (float)(loss * EPSd / (double)C + (1.0 - EPSd) * nll + corr);
}

extern "C" void kernel_launch(void* const* d_in, const int* in_sizes, int n_in,
                              void* d_out, int out_size) {
    const float*     out = (const float*)d_in[0];
    const long long* tgt = (const long long*)d_in[1];
    const int N = in_sizes[1];
    const int C = in_sizes[0] / N;

    zero_acc_kernel<<<1, 32>>>();
    const int blocks = (N + 7) / 8;                 // 8 warps per block, 1 row/warp
    lsce_main_kernel<<<blocks, 256>>>(out, tgt, N, C);
    finalize_kernel<<<1, 1>>>((float*)d_out, N, C);
}

// round 2
// speedup vs baseline: 1.2106x; 1.2106x over previous
#include <cuda_runtime.h>
#include <math.h>

// Per-block partials: [block][0]=Σ(C*lse - sumx), [1]=Σ(picked - lse), [2]=Σ correction
#define NBLK 2048
#define WPB  8            // warps per block
__device__ double g_part[NBLK][3];

// One warp per row, each warp loops over rows with stride = total warps.
// Fast path specialized for C == 1000 (nv = 250 float4: 7 full iters + 26-lane tail).
__global__ void __launch_bounds__(256)
lsce_main_kernel(const float* __restrict__ outp,
                 const long long* __restrict__ tgt,
                 int N, int C) {
    const int lane  = threadIdx.x & 31;
    const int wib   = threadIdx.x >> 5;
    const int gwarp = blockIdx.x * WPB + wib;
    const int nwarp = gridDim.x * WPB;
    const int nv    = C >> 2;

    double a0 = 0.0, a1 = 0.0, a2 = 0.0;

    if (nv == 250) {
        for (int row = gwarp; row < N; row += nwarp) {
            const float4* __restrict__ rp =
                reinterpret_cast<const float4*>(outp + (size_t)row * (size_t)C);
            const int t = (int)tgt[row];

            // Load burst: 7 unconditional + 1 tail (lane < 26).
            float4 v[8];
            #pragma unroll
            for (int k = 0; k < 7; k++) v[k] = __ldcs(&rp[lane + 32 * k]);
            const bool tail = lane < 26;
            if (tail) v[7] = __ldcs(&rp[224 + lane]);

            // Sweep 1: max/argmax (first occurrence), sum, picked.
            float m = -INFINITY;  int mi = 1000;
            float sumx = 0.f, picked = 0.f;
            #pragma unroll
            for (int k = 0; k < 8; k++) {
                if (k < 7 || tail) {
                    const int j = (k < 7) ? (lane + 32 * k) : (224 + lane);
                    const float x0 = v[k].x, x1 = v[k].y, x2 = v[k].z, x3 = v[k].w;
                    const int b = 4 * j;
                    sumx += (x0 + x1) + (x2 + x3);
                    if (x0 > m) { m = x0; mi = b;     }
                    if (x1 > m) { m = x1; mi = b + 1; }
                    if (x2 > m) { m = x2; mi = b + 2; }
                    if (x3 > m) { m = x3; mi = b + 3; }
                    if (t >= b && t < b + 4)
                        picked = (t == b) ? x0 : (t == b + 1) ? x1 : (t == b + 2) ? x2 : x3;
                }
            }

            #pragma unroll
            for (int off = 16; off; off >>= 1) {
                const float om = __shfl_xor_sync(0xffffffffu, m,  off);
                const int   oi = __shfl_xor_sync(0xffffffffu, mi, off);
                if (om > m || (om == m && oi < mi)) { m = om; mi = oi; }
                sumx   += __shfl_xor_sync(0xffffffffu, sumx,   off);
                picked += __shfl_xor_sync(0xffffffffu, picked, off);
            }

            // Sweep 2: Σ exp(x - m).
            float s = 0.f;
            #pragma unroll
            for (int k = 0; k < 8; k++) {
                if (k < 7 || tail) {
                    s += __expf(v[k].x - m) + __expf(v[k].y - m)
                       + __expf(v[k].z - m) + __expf(v[k].w - m);
                }
            }
            #pragma unroll
            for (int off = 16; off; off >>= 1)
                s += __shfl_xor_sync(0xffffffffu, s, off);

            if (lane == 0) {
                const float lse = m + __logf(s);
                a0 += (double)C * (double)lse - (double)sumx;
                a1 += (double)picked - (double)lse;
                if (row < C) {
                    const int lt = mi + t;
                    const int ad = abs(mi - t);
                    a2 += (lt >= 2) ? (0.1 * (1.0 / 0.32447699714575207))
                        : ((lt == 1 && ad != 1) ? -(0.1 * 0.5945275813408382) : 0.0);
                }
            }
        }
    } else {
        // Generic fallback (any C <= 4096), scalar loads.
        for (int row = gwarp; row < N; row += nwarp) {
            const float* rp = outp + (size_t)row * (size_t)C;
            const int t = (int)tgt[row];
            float m = -INFINITY; int mi = C;
            float sumx = 0.f, picked = 0.f;
            for (int j = lane; j < C; j += 32) {
                const float x = rp[j];
                sumx += x;
                if (x > m) { m = x; mi = j; }
                if (j == t) picked = x;
            }
            #pragma unroll
            for (int off = 16; off; off >>= 1) {
                const float om = __shfl_xor_sync(0xffffffffu, m,  off);
                const int   oi = __shfl_xor_sync(0xffffffffu, mi, off);
                if (om > m || (om == m && oi < mi)) { m = om; mi = oi; }
                sumx   += __shfl_xor_sync(0xffffffffu, sumx,   off);
                picked += __shfl_xor_sync(0xffffffffu, picked, off);
            }
            float s = 0.f;
            for (int j = lane; j < C; j += 32) s += __expf(rp[j] - m);
            #pragma unroll
            for (int off = 16; off; off >>= 1)
                s += __shfl_xor_sync(0xffffffffu, s, off);
            if (lane == 0) {
                const float lse = m + __logf(s);
                a0 += (double)C * (double)lse - (double)sumx;
                a1 += (double)picked - (double)lse;
                if (row < C) {
                    const int lt = mi + t;
                    const int ad = abs(mi - t);
                    a2 += (lt >= 2) ? (0.1 * (1.0 / 0.32447699714575207))
                        : ((lt == 1 && ad != 1) ? -(0.1 * 0.5945275813408382) : 0.0);
                }
            }
        }
    }

    // Block reduce (lane 0 of each warp holds the warp's accumulators).
    __shared__ double sh[WPB][3];
    if (lane == 0) { sh[wib][0] = a0; sh[wib][1] = a1; sh[wib][2] = a2; }
    __syncthreads();
    if (threadIdx.x == 0) {
        double b0 = 0.0, b1 = 0.0, b2 = 0.0;
        #pragma unroll
        for (int i = 0; i < WPB; i++) { b0 += sh[i][0]; b1 += sh[i][1]; b2 += sh[i][2]; }
        g_part[blockIdx.x][0] = b0;
        g_part[blockIdx.x][1] = b1;
        g_part[blockIdx.x][2] = b2;
    }
}

__global__ void __launch_bounds__(256)
finalize_kernel(float* __restrict__ outp, int N, int C) {
    __shared__ double sh[256][3];
    double a0 = 0.0, a1 = 0.0, a2 = 0.0;
    for (int i = threadIdx.x; i < NBLK; i += 256) {
        a0 += g_part[i][0]; a1 += g_part[i][1]; a2 += g_part[i][2];
    }
    sh[threadIdx.x][0] = a0; sh[threadIdx.x][1] = a1; sh[threadIdx.x][2] = a2;
    __syncthreads();
    for (int off = 128; off; off >>= 1) {
        if (threadIdx.x < off) {
            sh[threadIdx.x][0] += sh[threadIdx.x + off][0];
            sh[threadIdx.x][1] += sh[threadIdx.x + off][1];
            sh[threadIdx.x][2] += sh[threadIdx.x + off][2];
        }
        __syncthreads();
    }
    if (threadIdx.x == 0) {
        const double EPSd = 0.1;
        const double loss = sh[0][0] / (double)N;
        const double nll  = -(sh[0][1] / (double)N);
        const double corr = sh[0][2] / (double)C;
        outp[0] = (float)(loss * EPSd / (double)C + (1.0 - EPSd) * nll + corr);
    }
}

extern "C" void kernel_launch(void* const* d_in, const int* in_sizes, int n_in,
                              void* d_out, int out_size) {
    const float*     outp = (const float*)d_in[0];
    const long long* tgt  = (const long long*)d_in[1];
    const int N = in_sizes[1];
    const int C = in_sizes[0] / N;

    lsce_main_kernel<<<NBLK, 256>>>(outp, tgt, N, C);
    finalize_kernel<<<1, 256>>>((float*)d_out, N, C);
}